// round 7
// baseline (speedup 1.0000x reference)
#include <cuda_runtime.h>
#include <cuda_bf16.h>
#include <stdint.h>

// ---------------- problem constants ----------------
#define NBATCH 128
#define SEQ    2048
#define DIM    256          // K (features)
#define ADIM   128          // N (attention dim)
#define TILES  2048         // M-tiles of 128 rows
#define GRID   152
#define NTHR   512

// smem layout (bytes)
#define SM_WF     0                   // 131072: W fragments
#define OFF_SSC   131072              // float[4][128] score partials per colgroup
#define OFF_SE    (131072 + 2048)     // float[2][128] exp(score), double buffered
#define OFF_SRED  (131072 + 3072)     // float[256]
#define OFF_SBIAS (131072 + 4096)     // float[128]
#define OFF_SCV   (131072 + 4608)     // float[128]
#define SM_TOTAL  (131072 + 5632)

// ---------------- device scratch ----------------
__device__ float g_partial[TILES * DIM];          // 2 MB
__device__ float g_esum[TILES];
__device__ unsigned g_count;                      // monotonic ticket barrier

// ---------------- helpers ----------------
__device__ __forceinline__ uint32_t pkbf(float a, float b) {
    __nv_bfloat162 t = __floats2bfloat162_rn(a, b);
    return *(uint32_t*)&t;
}
__device__ __forceinline__ void split2(float a, float b, uint32_t& hi, uint32_t& lo) {
    float ra = __bfloat162float(__float2bfloat16(a));
    float rb = __bfloat162float(__float2bfloat16(b));
    hi = pkbf(a, b);
    lo = pkbf(a - ra, b - rb);
}
__device__ __forceinline__ void mma_bf16(float c[4], uint32_t a0, uint32_t a1,
                                         uint32_t a2, uint32_t a3,
                                         uint32_t b0, uint32_t b1) {
    asm volatile(
        "mma.sync.aligned.m16n8k16.row.col.f32.bf16.bf16.f32 "
        "{%0,%1,%2,%3}, {%4,%5,%6,%7}, {%8,%9}, {%0,%1,%2,%3};"
        : "+f"(c[0]), "+f"(c[1]), "+f"(c[2]), "+f"(c[3])
        : "r"(a0), "r"(a1), "r"(a2), "r"(a3), "r"(b0), "r"(b1));
}
__device__ __forceinline__ float fast_tanh(float v) {
    float e = __expf(2.0f * v);
    return 1.0f - __fdividef(2.0f, e + 1.0f);
}

// ---------------- fused persistent kernel ----------------
__global__ void __launch_bounds__(NTHR, 1)
attn_fused(const float* __restrict__ x,
           const float* __restrict__ w,
           const float* __restrict__ bias,
           const float* __restrict__ cvec,
           float* __restrict__ out)
{
    extern __shared__ char smem[];
    uint4* sWf   = (uint4*)(smem + SM_WF);
    float* sSc   = (float*)(smem + OFF_SSC);         // [4][128]
    float* sE0   = (float*)(smem + OFF_SE);          // [2][128]
    float* sRed  = (float*)(smem + OFF_SRED);        // [256]
    float* sBias = (float*)(smem + OFF_SBIAS);
    float* sCv   = (float*)(smem + OFF_SCV);

    const int tid   = threadIdx.x;
    const int wid   = tid >> 5;
    const int lane  = tid & 31;
    const int g     = lane >> 2;      // 0..7
    const int tig   = lane & 3;       // 0..3
    const int rowg  = wid & 3;        // row group: rows rowg*32 .. +32
    const int colg  = wid >> 2;       // col group: cols colg*32 .. +32

    const int d_ws = tid & 255;       // weighted-sum feature
    const int h_ws = tid >> 8;        // weighted-sum t-half

    // ---- build W fragments in smem (per-CTA, from global W) ----
    // frag[(j*16+nf)*32+lane] = {hi(w[k0,k0+1][n]), hi(w[k0+8,k0+9][n]), lo.., lo..}
    for (int idx = tid; idx < 16 * 16 * 32; idx += NTHR) {
        int ln = idx & 31, nf = (idx >> 5) & 15, j = idx >> 9;
        int gg = ln >> 2, tg = ln & 3;
        int n = nf * 8 + gg;
        int k0 = j * 16 + tg * 2;
        float w00 = w[(k0 + 0) * ADIM + n], w01 = w[(k0 + 1) * ADIM + n];
        float w80 = w[(k0 + 8) * ADIM + n], w81 = w[(k0 + 9) * ADIM + n];
        uint4 v;
        split2(w00, w01, v.x, v.z);
        split2(w80, w81, v.y, v.w);
        sWf[idx] = v;
    }
    if (tid < 128) { sBias[tid] = bias[tid]; sCv[tid] = cvec[tid]; }
    __syncthreads();

    int lastT = -1, lastbuf = 0, it = 0;

    for (int T = blockIdx.x; T < TILES; T += GRID, it++) {
        const int buf = it & 1;
        const size_t row0 = (size_t)T * 128;
        const int base_r = rowg * 32;
        const float* xa = x + (row0 + base_r + g) * DIM + 2 * tig;      // row g
        const float* xb = xa + (size_t)8 * DIM;                          // g+8
        const float* xc = xa + (size_t)16 * DIM;                         // g+16
        const float* xd = xa + (size_t)24 * DIM;                         // g+24

        const int Tprev = T - GRID;
        const bool havePrev = (it > 0);
        const float* xprev = x + ((size_t)(havePrev ? Tprev : T) * 128 + h_ws * 64) * DIM + d_ws;
        const float* sEp = sE0 + (buf ^ 1) * 128 + h_ws * 64;
        float wacc = 0.0f;

        float acc[2][4][4];
        #pragma unroll
        for (int rg = 0; rg < 2; rg++)
            #pragma unroll
            for (int nf = 0; nf < 4; nf++)
                #pragma unroll
                for (int c = 0; c < 4; c++) acc[rg][nf][c] = 0.0f;

        float2 na0 = *(const float2*)xa,       na1 = *(const float2*)(xa + 8);
        float2 nb0 = *(const float2*)xb,       nb1 = *(const float2*)(xb + 8);
        float2 nc0 = *(const float2*)xc,       nc1 = *(const float2*)(xc + 8);
        float2 nd0 = *(const float2*)xd,       nd1 = *(const float2*)(xd + 8);

        #pragma unroll 1
        for (int j = 0; j < 16; j++) {
            // prev-tile weighted-sum loads issued early (hide under MMAs)
            float wv[4];
            if (havePrev) {
                #pragma unroll
                for (int q = 0; q < 4; q++)
                    wv[q] = __ldg(xprev + (size_t)(j * 4 + q) * DIM);
            }

            float2 ca0 = na0, ca1 = na1, cb0 = nb0, cb1 = nb1;
            float2 cc0 = nc0, cc1 = nc1, cd0 = nd0, cd1 = nd1;
            if (j < 15) {
                int o = (j + 1) * 16;
                na0 = *(const float2*)(xa + o); na1 = *(const float2*)(xa + o + 8);
                nb0 = *(const float2*)(xb + o); nb1 = *(const float2*)(xb + o + 8);
                nc0 = *(const float2*)(xc + o); nc1 = *(const float2*)(xc + o + 8);
                nd0 = *(const float2*)(xd + o); nd1 = *(const float2*)(xd + o + 8);
            }

            uint32_t ah0, ah1, ah2, ah3, al0, al1, al2, al3;   // rowgroup 0
            uint32_t bh0, bh1, bh2, bh3, bl0, bl1, bl2, bl3;   // rowgroup 1
            split2(ca0.x, ca0.y, ah0, al0);
            split2(cb0.x, cb0.y, ah1, al1);
            split2(ca1.x, ca1.y, ah2, al2);
            split2(cb1.x, cb1.y, ah3, al3);
            split2(cc0.x, cc0.y, bh0, bl0);
            split2(cd0.x, cd0.y, bh1, bl1);
            split2(cc1.x, cc1.y, bh2, bl2);
            split2(cd1.x, cd1.y, bh3, bl3);

            const uint4* bp = sWf + (j * 16 + colg * 4) * 32 + lane;
            #pragma unroll
            for (int nf = 0; nf < 4; nf++) {
                uint4 B = bp[nf * 32];
                mma_bf16(acc[0][nf], ah0, ah1, ah2, ah3, B.x, B.y);   // hi*hi
                mma_bf16(acc[0][nf], ah0, ah1, ah2, ah3, B.z, B.w);   // hi*lo
                mma_bf16(acc[0][nf], al0, al1, al2, al3, B.x, B.y);   // lo*hi
                mma_bf16(acc[1][nf], bh0, bh1, bh2, bh3, B.x, B.y);
                mma_bf16(acc[1][nf], bh0, bh1, bh2, bh3, B.z, B.w);
                mma_bf16(acc[1][nf], bl0, bl1, bl2, bl3, B.x, B.y);
            }

            if (havePrev) {
                #pragma unroll
                for (int q = 0; q < 4; q++)
                    wacc = fmaf(sEp[j * 4 + q], wv[q], wacc);
            }
        }

        if (havePrev && h_ws == 0) sRed[d_ws] = wacc;

        // ---- score partials over this warp's 32 columns, 32 rows ----
        #pragma unroll
        for (int rg = 0; rg < 2; rg++) {
            float p1 = 0.0f, p2 = 0.0f;
            #pragma unroll
            for (int nf = 0; nf < 4; nf++) {
                int col = colg * 32 + nf * 8 + 2 * tig;
                p1 += sCv[col]     * fast_tanh(acc[rg][nf][0] + sBias[col]);
                p1 += sCv[col + 1] * fast_tanh(acc[rg][nf][1] + sBias[col + 1]);
                p2 += sCv[col]     * fast_tanh(acc[rg][nf][2] + sBias[col]);
                p2 += sCv[col + 1] * fast_tanh(acc[rg][nf][3] + sBias[col + 1]);
            }
            p1 += __shfl_xor_sync(0xFFFFFFFFu, p1, 1);
            p1 += __shfl_xor_sync(0xFFFFFFFFu, p1, 2);
            p2 += __shfl_xor_sync(0xFFFFFFFFu, p2, 1);
            p2 += __shfl_xor_sync(0xFFFFFFFFu, p2, 2);
            if (tig == 0) {
                int r = base_r + rg * 16 + g;
                sSc[colg * 128 + r]     = p1;
                sSc[colg * 128 + r + 8] = p2;
            }
        }
        __syncthreads();   // sync #1: sRed(h0) + score partials visible

        if (havePrev && h_ws == 1)
            g_partial[(size_t)Tprev * DIM + d_ws] = sRed[d_ws] + wacc;

        if (tid < 128) {
            float s = sSc[tid] + sSc[128 + tid] + sSc[256 + tid] + sSc[384 + tid];
            sE0[buf * 128 + tid] = __expf(s);
        }
        __syncthreads();   // sync #2: sE[buf] visible

        if (tid < 32) {
            const float* sEc = sE0 + buf * 128;
            float e = sEc[tid] + sEc[tid + 32] + sEc[tid + 64] + sEc[tid + 96];
            e += __shfl_xor_sync(0xFFFFFFFFu, e, 16);
            e += __shfl_xor_sync(0xFFFFFFFFu, e, 8);
            e += __shfl_xor_sync(0xFFFFFFFFu, e, 4);
            e += __shfl_xor_sync(0xFFFFFFFFu, e, 2);
            e += __shfl_xor_sync(0xFFFFFFFFu, e, 1);
            if (tid == 0) g_esum[T] = e;
        }

        lastT = T; lastbuf = buf;
    }

    // ---- drain: weighted sum for the final tile ----
    {
        const float* sEc = sE0 + lastbuf * 128 + h_ws * 64;
        const float* xp = x + ((size_t)lastT * 128 + h_ws * 64) * DIM + d_ws;
        float wacc = 0.0f;
        #pragma unroll 16
        for (int t = 0; t < 64; t++)
            wacc = fmaf(sEc[t], __ldg(xp + (size_t)t * DIM), wacc);
        if (h_ws == 0) sRed[d_ws] = wacc;
        __syncthreads();
        if (h_ws == 1)
            g_partial[(size_t)lastT * DIM + d_ws] = sRed[d_ws] + wacc;
    }

    // ---- grid-wide ticket barrier (monotonic: graph-replay safe) ----
    __threadfence();
    __syncthreads();
    if (tid == 0) {
        unsigned t = atomicAdd(&g_count, 1u);
        unsigned target = (t / GRID + 1u) * GRID;
        while (atomicAdd(&g_count, 0u) < target) { __nanosleep(64); }
    }
    __syncthreads();

    // ---- finish: combine 16 splits per batch ----
    if (blockIdx.x < NBATCH && tid < DIM) {
        const int b = blockIdx.x;
        float s = 0.0f, es = 0.0f;
        #pragma unroll
        for (int sp = 0; sp < 16; sp++) {
            s  += __ldcg(&g_partial[(size_t)(b * 16 + sp) * DIM + tid]);
            es += __ldcg(&g_esum[b * 16 + sp]);
        }
        out[b * DIM + tid] = s / (es + 1e-10f);
    }
}

extern "C" void kernel_launch(void* const* d_in, const int* in_sizes, int n_in,
                              void* d_out, int out_size)
{
    const float* x    = (const float*)d_in[0];
    const float* w    = (const float*)d_in[1];
    const float* bias = (const float*)d_in[2];
    const float* cvec = (const float*)d_in[3];
    float* out = (float*)d_out;

    cudaFuncSetAttribute(attn_fused, cudaFuncAttributeMaxDynamicSharedMemorySize, SM_TOTAL);
    attn_fused<<<GRID, NTHR, SM_TOTAL>>>(x, w, bias, cvec, out);
}

// round 8
// speedup vs baseline: 1.1149x; 1.1149x over previous
#include <cuda_runtime.h>
#include <cuda_bf16.h>
#include <stdint.h>

// ---------------- problem constants ----------------
#define NBATCH 128
#define SEQ    2048
#define DIM    256          // K (features)
#define ADIM   128          // N (attention dim)
#define TILES  2048         // M-tiles of 128 rows
#define GRID   152
#define NTHR   512

// smem layout (bytes)
#define SM_WF     0                       // 131072: W fragments
#define SM_AH     131072                  // 32768: X-tile bf16 hi, [128r][128k] swizzled
#define SM_AL     (131072 + 32768)        // 32768: X-tile bf16 lo
#define OFF_SSC   (131072 + 65536)        // float[4][128] score partials
#define OFF_SE    (OFF_SSC + 2048)        // float[2][128] exp(score), double buffered
#define OFF_SRED  (OFF_SE + 1024)         // float[256]
#define OFF_SBIAS (OFF_SRED + 1024)       // float[128]
#define OFF_SCV   (OFF_SBIAS + 512)       // float[128]
#define SM_TOTAL  (OFF_SCV + 512)         // 201728

// ---------------- device scratch ----------------
__device__ float g_partial[TILES * DIM];          // 2 MB
__device__ float g_esum[TILES];
__device__ unsigned g_count;                      // monotonic ticket barrier

// ---------------- helpers ----------------
__device__ __forceinline__ uint32_t smem_u32(const void* p) {
    uint32_t a;
    asm("{ .reg .u64 t; cvta.to.shared.u64 t, %1; cvt.u32.u64 %0, t; }" : "=r"(a) : "l"(p));
    return a;
}
__device__ __forceinline__ uint32_t pkbf(float a, float b) {
    __nv_bfloat162 t = __floats2bfloat162_rn(a, b);
    return *(uint32_t*)&t;
}
__device__ __forceinline__ void split2(float a, float b, uint32_t& hi, uint32_t& lo) {
    float ra = __bfloat162float(__float2bfloat16(a));
    float rb = __bfloat162float(__float2bfloat16(b));
    hi = pkbf(a, b);
    lo = pkbf(a - ra, b - rb);
}
__device__ __forceinline__ void mma_bf16(float c[4], uint32_t a0, uint32_t a1,
                                         uint32_t a2, uint32_t a3,
                                         uint32_t b0, uint32_t b1) {
    asm volatile(
        "mma.sync.aligned.m16n8k16.row.col.f32.bf16.bf16.f32 "
        "{%0,%1,%2,%3}, {%4,%5,%6,%7}, {%8,%9}, {%0,%1,%2,%3};"
        : "+f"(c[0]), "+f"(c[1]), "+f"(c[2]), "+f"(c[3])
        : "r"(a0), "r"(a1), "r"(a2), "r"(a3), "r"(b0), "r"(b1));
}
__device__ __forceinline__ void ldmA(uint32_t& r0, uint32_t& r1, uint32_t& r2,
                                     uint32_t& r3, uint32_t addr) {
    asm volatile("ldmatrix.sync.aligned.m8n8.x4.shared.b16 {%0,%1,%2,%3}, [%4];"
        : "=r"(r0), "=r"(r1), "=r"(r2), "=r"(r3) : "r"(addr));
}
__device__ __forceinline__ float fast_tanh(float v) {
    float e = __expf(2.0f * v);
    return 1.0f - __fdividef(2.0f, e + 1.0f);
}

// ---------------- fused persistent kernel ----------------
__global__ void __launch_bounds__(NTHR, 1)
attn_fused(const float* __restrict__ x,
           const float* __restrict__ w,
           const float* __restrict__ bias,
           const float* __restrict__ cvec,
           float* __restrict__ out)
{
    extern __shared__ char smem[];
    uint4* sWf   = (uint4*)(smem + SM_WF);
    float* sSc   = (float*)(smem + OFF_SSC);         // [4][128]
    float* sE0   = (float*)(smem + OFF_SE);          // [2][128]
    float* sRed  = (float*)(smem + OFF_SRED);        // [256]
    float* sBias = (float*)(smem + OFF_SBIAS);
    float* sCv   = (float*)(smem + OFF_SCV);

    const uint32_t sbase = smem_u32(smem);
    const uint32_t AH = sbase + SM_AH, AL = sbase + SM_AL;

    const int tid   = threadIdx.x;
    const int wid   = tid >> 5;
    const int lane  = tid & 31;
    const int g     = lane >> 2;      // 0..7
    const int tig   = lane & 3;       // 0..3
    const int rowg  = wid & 3;        // warp rows: rowg*32 .. +32
    const int colg  = wid >> 2;       // warp cols: colg*32 .. +32

    const int d_ws = tid & 255;       // weighted-sum feature
    const int h_ws = tid >> 8;        // weighted-sum t-half

    // ---- build W fragments in smem (once) ----
    for (int idx = tid; idx < 16 * 16 * 32; idx += NTHR) {
        int ln = idx & 31, nf = (idx >> 5) & 15, j = idx >> 9;
        int gg = ln >> 2, tg = ln & 3;
        int n = nf * 8 + gg;
        int k0 = j * 16 + tg * 2;
        float w00 = w[(k0 + 0) * ADIM + n], w01 = w[(k0 + 1) * ADIM + n];
        float w80 = w[(k0 + 8) * ADIM + n], w81 = w[(k0 + 9) * ADIM + n];
        uint4 v;
        split2(w00, w01, v.x, v.z);
        split2(w80, w81, v.y, v.w);
        sWf[idx] = v;
    }
    if (tid < 128) { sBias[tid] = bias[tid]; sCv[tid] = cvec[tid]; }

    // ldmatrix per-thread constants: mchunk0 row rA, mchunk1 row rB
    const int rA = rowg * 32 + (lane & 15);
    const int rB = rA + 16;
    const uint32_t baseHA = AH + rA * 256, baseLA = AL + rA * 256;
    const uint32_t baseHB = AH + rB * 256, baseLB = AL + rB * 256;
    const int swA = rA & 7, swB = rB & 7;
    const int khi = lane >> 4;        // 0/1 -> k+0 / k+8 within kstep

    int lastT = -1, lastbuf = 0, it = 0;

    for (int T = blockIdx.x; T < TILES; T += GRID, it++) {
        const int buf = it & 1;
        const size_t row0 = (size_t)T * 128;

        const int Tprev = T - GRID;
        const bool havePrev = (it > 0);
        const float* xprev = x + ((size_t)(havePrev ? Tprev : T) * 128 + h_ws * 64) * DIM + d_ws;
        const float* sEp = sE0 + (buf ^ 1) * 128 + h_ws * 64;
        float wacc = 0.0f;

        float acc[2][4][4];
        #pragma unroll
        for (int rg = 0; rg < 2; rg++)
            #pragma unroll
            for (int nf = 0; nf < 4; nf++)
                #pragma unroll
                for (int c = 0; c < 4; c++) acc[rg][nf][c] = 0.0f;

        #pragma unroll 1
        for (int h = 0; h < 2; h++) {
            __syncthreads();   // protect A planes (prev reads done) / W-frags ready on it=0

            // ---- stage half h: rows wid*8..+7, k = h*128..+127, coalesced ----
            {
                const int g2 = lane >> 1;
                const uint32_t soff0 = (uint32_t)(lane & 1) * 8;
                const float* xr = x + (row0 + wid * 8) * DIM + h * 128 + 4 * lane;
                #pragma unroll
                for (int rr = 0; rr < 8; rr++) {
                    float4 v = *(const float4*)(xr + (size_t)rr * DIM);
                    int r = wid * 8 + rr;
                    uint32_t off = (uint32_t)r * 256 + ((uint32_t)(g2 ^ (r & 7)) << 4) + soff0;
                    uint32_t h01, l01, h23, l23;
                    split2(v.x, v.y, h01, l01);
                    split2(v.z, v.w, h23, l23);
                    *(uint2*)(smem + SM_AH + off) = make_uint2(h01, h23);
                    *(uint2*)(smem + SM_AL + off) = make_uint2(l01, l23);
                }
            }
            __syncthreads();

            // ---- 8 k-steps on this half ----
            #pragma unroll 1
            for (int jl = 0; jl < 8; jl++) {
                const int jj = h * 8 + jl;

                // prev-tile weighted-sum loads issued early
                float wv[4];
                if (havePrev) {
                    #pragma unroll
                    for (int q = 0; q < 4; q++)
                        wv[q] = __ldg(xprev + (size_t)(jj * 4 + q) * DIM);
                }

                const uint32_t gsw = (uint32_t)((jl * 2 + khi));
                uint32_t ah0, ah1, ah2, ah3, al0, al1, al2, al3;
                uint32_t bh0, bh1, bh2, bh3, bl0, bl1, bl2, bl3;
                ldmA(ah0, ah1, ah2, ah3, baseHA + ((gsw ^ (uint32_t)swA) << 4));
                ldmA(al0, al1, al2, al3, baseLA + ((gsw ^ (uint32_t)swA) << 4));
                ldmA(bh0, bh1, bh2, bh3, baseHB + ((gsw ^ (uint32_t)swB) << 4));
                ldmA(bl0, bl1, bl2, bl3, baseLB + ((gsw ^ (uint32_t)swB) << 4));

                const uint4* bp = sWf + (jj * 16 + colg * 4) * 32 + lane;
                #pragma unroll
                for (int nf = 0; nf < 4; nf++) {
                    uint4 B = bp[nf * 32];
                    mma_bf16(acc[0][nf], ah0, ah1, ah2, ah3, B.x, B.y);   // hi*hi
                    mma_bf16(acc[0][nf], ah0, ah1, ah2, ah3, B.z, B.w);   // hi*lo
                    mma_bf16(acc[0][nf], al0, al1, al2, al3, B.x, B.y);   // lo*hi
                    mma_bf16(acc[1][nf], bh0, bh1, bh2, bh3, B.x, B.y);
                    mma_bf16(acc[1][nf], bh0, bh1, bh2, bh3, B.z, B.w);
                    mma_bf16(acc[1][nf], bl0, bl1, bl2, bl3, B.x, B.y);
                }

                if (havePrev) {
                    #pragma unroll
                    for (int q = 0; q < 4; q++)
                        wacc = fmaf(sEp[jj * 4 + q], wv[q], wacc);
                }
            }
        }

        if (havePrev && h_ws == 0) sRed[d_ws] = wacc;

        // ---- score partials over this warp's 32 cols x 32 rows ----
        #pragma unroll
        for (int rg = 0; rg < 2; rg++) {
            float p1 = 0.0f, p2 = 0.0f;
            #pragma unroll
            for (int nf = 0; nf < 4; nf++) {
                int col = colg * 32 + nf * 8 + 2 * tig;
                p1 += sCv[col]     * fast_tanh(acc[rg][nf][0] + sBias[col]);
                p1 += sCv[col + 1] * fast_tanh(acc[rg][nf][1] + sBias[col + 1]);
                p2 += sCv[col]     * fast_tanh(acc[rg][nf][2] + sBias[col]);
                p2 += sCv[col + 1] * fast_tanh(acc[rg][nf][3] + sBias[col + 1]);
            }
            p1 += __shfl_xor_sync(0xFFFFFFFFu, p1, 1);
            p1 += __shfl_xor_sync(0xFFFFFFFFu, p1, 2);
            p2 += __shfl_xor_sync(0xFFFFFFFFu, p2, 1);
            p2 += __shfl_xor_sync(0xFFFFFFFFu, p2, 2);
            if (tig == 0) {
                int r = rowg * 32 + rg * 16 + g;
                sSc[colg * 128 + r]     = p1;
                sSc[colg * 128 + r + 8] = p2;
            }
        }
        __syncthreads();   // sync: sRed(h0) + score partials visible

        if (havePrev && h_ws == 1)
            g_partial[(size_t)Tprev * DIM + d_ws] = sRed[d_ws] + wacc;

        if (tid < 128) {
            float s = sSc[tid] + sSc[128 + tid] + sSc[256 + tid] + sSc[384 + tid];
            sE0[buf * 128 + tid] = __expf(s);
        }
        __syncthreads();   // sync: sE[buf] visible

        if (tid < 32) {
            const float* sEc = sE0 + buf * 128;
            float e = sEc[tid] + sEc[tid + 32] + sEc[tid + 64] + sEc[tid + 96];
            e += __shfl_xor_sync(0xFFFFFFFFu, e, 16);
            e += __shfl_xor_sync(0xFFFFFFFFu, e, 8);
            e += __shfl_xor_sync(0xFFFFFFFFu, e, 4);
            e += __shfl_xor_sync(0xFFFFFFFFu, e, 2);
            e += __shfl_xor_sync(0xFFFFFFFFu, e, 1);
            if (tid == 0) g_esum[T] = e;
        }

        lastT = T; lastbuf = buf;
    }

    // ---- drain: weighted sum for the final tile ----
    {
        const float* sEc = sE0 + lastbuf * 128 + h_ws * 64;
        const float* xp = x + ((size_t)lastT * 128 + h_ws * 64) * DIM + d_ws;
        float wacc = 0.0f;
        #pragma unroll 16
        for (int t = 0; t < 64; t++)
            wacc = fmaf(sEc[t], __ldg(xp + (size_t)t * DIM), wacc);
        if (h_ws == 0) sRed[d_ws] = wacc;
        __syncthreads();
        if (h_ws == 1)
            g_partial[(size_t)lastT * DIM + d_ws] = sRed[d_ws] + wacc;
    }

    // ---- grid-wide ticket barrier (monotonic: graph-replay safe) ----
    __threadfence();
    __syncthreads();
    if (tid == 0) {
        unsigned t = atomicAdd(&g_count, 1u);
        unsigned target = (t / GRID + 1u) * GRID;
        while (atomicAdd(&g_count, 0u) < target) { __nanosleep(64); }
    }
    __syncthreads();

    // ---- finish: combine 16 splits per batch ----
    if (blockIdx.x < NBATCH && tid < DIM) {
        const int b = blockIdx.x;
        float s = 0.0f, es = 0.0f;
        #pragma unroll
        for (int sp = 0; sp < 16; sp++) {
            s  += __ldcg(&g_partial[(size_t)(b * 16 + sp) * DIM + tid]);
            es += __ldcg(&g_esum[b * 16 + sp]);
        }
        out[b * DIM + tid] = s / (es + 1e-10f);
    }
}

extern "C" void kernel_launch(void* const* d_in, const int* in_sizes, int n_in,
                              void* d_out, int out_size)
{
    const float* x    = (const float*)d_in[0];
    const float* w    = (const float*)d_in[1];
    const float* bias = (const float*)d_in[2];
    const float* cvec = (const float*)d_in[3];
    float* out = (float*)d_out;

    cudaFuncSetAttribute(attn_fused, cudaFuncAttributeMaxDynamicSharedMemorySize, SM_TOTAL);
    attn_fused<<<GRID, NTHR, SM_TOTAL>>>(x, w, bias, cvec, out);
}

// round 9
// speedup vs baseline: 1.2281x; 1.1016x over previous
#include <cuda_runtime.h>
#include <cuda_bf16.h>
#include <stdint.h>

// ---------------- problem constants ----------------
#define NBATCH 128
#define SEQ    2048
#define DIM    256          // K (features)
#define ADIM   128          // N (attention dim)
#define TILES  2048         // M-tiles of 128 rows
#define GRID   152
#define NTHR   512

// smem layout (bytes)
#define SM_WF     0                       // 131072: W fragments
#define SM_A      131072                  // 2 bufs x (hi 16K + lo 16K) = 65536
#define OFF_SSC   (131072 + 65536)        // float[4][128] score partials
#define OFF_SE    (OFF_SSC + 2048)        // float[2][128] exp(score), double buffered
#define OFF_SRED  (OFF_SE + 1024)         // float[256]
#define OFF_SBIAS (OFF_SRED + 1024)       // float[128]
#define OFF_SCV   (OFF_SBIAS + 512)       // float[128]
#define SM_TOTAL  (OFF_SCV + 512)

// ---------------- device scratch ----------------
__device__ float g_partial[TILES * DIM];          // 2 MB
__device__ float g_esum[TILES];
__device__ unsigned g_count;                      // monotonic ticket barrier

// ---------------- helpers ----------------
__device__ __forceinline__ uint32_t smem_u32(const void* p) {
    uint32_t a;
    asm("{ .reg .u64 t; cvta.to.shared.u64 t, %1; cvt.u32.u64 %0, t; }" : "=r"(a) : "l"(p));
    return a;
}
__device__ __forceinline__ uint32_t pkbf(float a, float b) {
    __nv_bfloat162 t = __floats2bfloat162_rn(a, b);
    return *(uint32_t*)&t;
}
__device__ __forceinline__ void split2(float a, float b, uint32_t& hi, uint32_t& lo) {
    float ra = __bfloat162float(__float2bfloat16(a));
    float rb = __bfloat162float(__float2bfloat16(b));
    hi = pkbf(a, b);
    lo = pkbf(a - ra, b - rb);
}
__device__ __forceinline__ void mma_bf16(float c[4], uint32_t a0, uint32_t a1,
                                         uint32_t a2, uint32_t a3,
                                         uint32_t b0, uint32_t b1) {
    asm volatile(
        "mma.sync.aligned.m16n8k16.row.col.f32.bf16.bf16.f32 "
        "{%0,%1,%2,%3}, {%4,%5,%6,%7}, {%8,%9}, {%0,%1,%2,%3};"
        : "+f"(c[0]), "+f"(c[1]), "+f"(c[2]), "+f"(c[3])
        : "r"(a0), "r"(a1), "r"(a2), "r"(a3), "r"(b0), "r"(b1));
}
__device__ __forceinline__ void ldmA(uint32_t& r0, uint32_t& r1, uint32_t& r2,
                                     uint32_t& r3, uint32_t addr) {
    asm volatile("ldmatrix.sync.aligned.m8n8.x4.shared.b16 {%0,%1,%2,%3}, [%4];"
        : "=r"(r0), "=r"(r1), "=r"(r2), "=r"(r3) : "r"(addr));
}
__device__ __forceinline__ float fast_tanh(float v) {
    float e = __expf(2.0f * v);
    return 1.0f - __fdividef(2.0f, e + 1.0f);
}

// ---------------- fused persistent kernel ----------------
__global__ void __launch_bounds__(NTHR, 1)
attn_fused(const float* __restrict__ x,
           const float* __restrict__ w,
           const float* __restrict__ bias,
           const float* __restrict__ cvec,
           float* __restrict__ out)
{
    extern __shared__ char smem[];
    uint4* sWf   = (uint4*)(smem + SM_WF);
    float* sSc   = (float*)(smem + OFF_SSC);         // [4][128]
    float* sE0   = (float*)(smem + OFF_SE);          // [2][128]
    float* sRed  = (float*)(smem + OFF_SRED);        // [256]
    float* sBias = (float*)(smem + OFF_SBIAS);
    float* sCv   = (float*)(smem + OFF_SCV);

    const uint32_t sbase = smem_u32(smem);

    const int tid   = threadIdx.x;
    const int wid   = tid >> 5;
    const int lane  = tid & 31;
    const int g     = lane >> 2;      // 0..7
    const int tig   = lane & 3;       // 0..3
    const int rowg  = wid & 3;        // warp rows: rowg*32 .. +32
    const int colg  = wid >> 2;       // warp cols: colg*32 .. +32

    const int d_ws = tid & 255;       // weighted-sum feature
    const int h_ws = tid >> 8;        // weighted-sum t-half

    // ---- build W fragments in smem (once) ----
    for (int idx = tid; idx < 16 * 16 * 32; idx += NTHR) {
        int ln = idx & 31, nf = (idx >> 5) & 15, j = idx >> 9;
        int gg = ln >> 2, tg = ln & 3;
        int n = nf * 8 + gg;
        int k0 = j * 16 + tg * 2;
        float w00 = w[(k0 + 0) * ADIM + n], w01 = w[(k0 + 1) * ADIM + n];
        float w80 = w[(k0 + 8) * ADIM + n], w81 = w[(k0 + 9) * ADIM + n];
        uint4 v;
        split2(w00, w01, v.x, v.z);
        split2(w80, w81, v.y, v.w);
        sWf[idx] = v;
    }
    if (tid < 128) { sBias[tid] = bias[tid]; sCv[tid] = cvec[tid]; }

    // staging constants: per pass p (0..3): row = wid*8 + p*2 + (lane>>4),
    // k-chunk-local float4 at 4*(lane&15); 8B store, group = (lane&15)>>1
    const int st_rl   = lane >> 4;                 // row parity within pass
    const int st_kf   = (lane & 15) * 4;           // k offset (floats)
    const uint32_t st_g = (uint32_t)((lane & 15) >> 1);
    const uint32_t st_s = (uint32_t)(lane & 1) * 8;

    // ldmatrix constants
    const int rA = rowg * 32 + (lane & 15);
    const int rB = rA + 16;
    const int swA = rA & 7, swB = rB & 7;
    const int khi = lane >> 4;

    int lastT = -1, lastbuf = 0, it = 0;

    for (int T = blockIdx.x; T < TILES; T += GRID, it++) {
        const int buf = it & 1;
        const size_t row0 = (size_t)T * 128;

        const int Tprev = T - GRID;
        const bool havePrev = (it > 0);
        const float* xprev = x + ((size_t)(havePrev ? Tprev : T) * 128 + h_ws * 64) * DIM + d_ws;
        const float* sEp = sE0 + (buf ^ 1) * 128 + h_ws * 64;
        float wacc = 0.0f;

        float acc[2][4][4];
        #pragma unroll
        for (int rg = 0; rg < 2; rg++)
            #pragma unroll
            for (int nf = 0; nf < 4; nf++)
                #pragma unroll
                for (int c = 0; c < 4; c++) acc[rg][nf][c] = 0.0f;

        // ---- prologue: stage chunk 0 into A-buf 0 ----
        {
            float4 lv[4];
            #pragma unroll
            for (int p = 0; p < 4; p++) {
                int r = wid * 8 + p * 2 + st_rl;
                lv[p] = *(const float4*)(x + (row0 + r) * DIM + st_kf);
            }
            #pragma unroll
            for (int p = 0; p < 4; p++) {
                int r = wid * 8 + p * 2 + st_rl;
                uint32_t off = (uint32_t)r * 128 + ((st_g ^ (uint32_t)(r & 7)) << 4) + st_s;
                uint32_t h01, l01, h23, l23;
                split2(lv[p].x, lv[p].y, h01, l01);
                split2(lv[p].z, lv[p].w, h23, l23);
                *(uint2*)(smem + SM_A + off) = make_uint2(h01, h23);
                *(uint2*)(smem + SM_A + 16384 + off) = make_uint2(l01, l23);
            }
        }
        __syncthreads();

        // ---- 4 chunks of 64 k, double buffered ----
        #pragma unroll 1
        for (int c = 0; c < 4; c++) {
            const int ab = c & 1;
            const uint32_t AHb = sbase + SM_A + (uint32_t)ab * 32768;
            const uint32_t ALb = AHb + 16384;

            // issue next chunk's loads
            float4 lv[4];
            if (c < 3) {
                const float* xs = x + row0 * DIM + (c + 1) * 64 + st_kf;
                #pragma unroll
                for (int p = 0; p < 4; p++) {
                    int r = wid * 8 + p * 2 + st_rl;
                    lv[p] = *(const float4*)(xs + (size_t)r * DIM);
                }
            }

            #pragma unroll
            for (int jl = 0; jl < 4; jl++) {
                const int jj = c * 4 + jl;

                float wv[4];
                if (havePrev) {
                    #pragma unroll
                    for (int q = 0; q < 4; q++)
                        wv[q] = __ldg(xprev + (size_t)(jj * 4 + q) * DIM);
                }

                const uint32_t gsw = (uint32_t)(jl * 2 + khi);
                uint32_t ah0, ah1, ah2, ah3, al0, al1, al2, al3;
                uint32_t bh0, bh1, bh2, bh3, bl0, bl1, bl2, bl3;
                ldmA(ah0, ah1, ah2, ah3, AHb + rA * 128 + ((gsw ^ (uint32_t)swA) << 4));
                ldmA(al0, al1, al2, al3, ALb + rA * 128 + ((gsw ^ (uint32_t)swA) << 4));
                ldmA(bh0, bh1, bh2, bh3, AHb + rB * 128 + ((gsw ^ (uint32_t)swB) << 4));
                ldmA(bl0, bl1, bl2, bl3, ALb + rB * 128 + ((gsw ^ (uint32_t)swB) << 4));

                const uint4* bp = sWf + (jj * 16 + colg * 4) * 32 + lane;
                #pragma unroll
                for (int nf = 0; nf < 4; nf++) {
                    uint4 B = bp[nf * 32];
                    mma_bf16(acc[0][nf], ah0, ah1, ah2, ah3, B.x, B.y);   // hi*hi
                    mma_bf16(acc[0][nf], ah0, ah1, ah2, ah3, B.z, B.w);   // hi*lo
                    mma_bf16(acc[0][nf], al0, al1, al2, al3, B.x, B.y);   // lo*hi
                    mma_bf16(acc[1][nf], bh0, bh1, bh2, bh3, B.x, B.y);
                    mma_bf16(acc[1][nf], bh0, bh1, bh2, bh3, B.z, B.w);
                    mma_bf16(acc[1][nf], bl0, bl1, bl2, bl3, B.x, B.y);
                }

                if (havePrev) {
                    #pragma unroll
                    for (int q = 0; q < 4; q++)
                        wacc = fmaf(sEp[jj * 4 + q], wv[q], wacc);
                }

                // mid-chunk: convert + STS next chunk into other buffer
                if (jl == 1 && c < 3) {
                    char* dst = smem + SM_A + (size_t)(ab ^ 1) * 32768;
                    #pragma unroll
                    for (int p = 0; p < 4; p++) {
                        int r = wid * 8 + p * 2 + st_rl;
                        uint32_t off = (uint32_t)r * 128 + ((st_g ^ (uint32_t)(r & 7)) << 4) + st_s;
                        uint32_t h01, l01, h23, l23;
                        split2(lv[p].x, lv[p].y, h01, l01);
                        split2(lv[p].z, lv[p].w, h23, l23);
                        *(uint2*)(dst + off) = make_uint2(h01, h23);
                        *(uint2*)(dst + 16384 + off) = make_uint2(l01, l23);
                    }
                }
            }
            __syncthreads();   // chunk boundary: STS(c+1) visible, buf reads done
        }

        if (havePrev && h_ws == 0) sRed[d_ws] = wacc;

        // ---- score partials over this warp's 32 cols x 32 rows ----
        #pragma unroll
        for (int rg = 0; rg < 2; rg++) {
            float p1 = 0.0f, p2 = 0.0f;
            #pragma unroll
            for (int nf = 0; nf < 4; nf++) {
                int col = colg * 32 + nf * 8 + 2 * tig;
                p1 += sCv[col]     * fast_tanh(acc[rg][nf][0] + sBias[col]);
                p1 += sCv[col + 1] * fast_tanh(acc[rg][nf][1] + sBias[col + 1]);
                p2 += sCv[col]     * fast_tanh(acc[rg][nf][2] + sBias[col]);
                p2 += sCv[col + 1] * fast_tanh(acc[rg][nf][3] + sBias[col + 1]);
            }
            p1 += __shfl_xor_sync(0xFFFFFFFFu, p1, 1);
            p1 += __shfl_xor_sync(0xFFFFFFFFu, p1, 2);
            p2 += __shfl_xor_sync(0xFFFFFFFFu, p2, 1);
            p2 += __shfl_xor_sync(0xFFFFFFFFu, p2, 2);
            if (tig == 0) {
                int r = rowg * 32 + rg * 16 + g;
                sSc[colg * 128 + r]     = p1;
                sSc[colg * 128 + r + 8] = p2;
            }
        }
        __syncthreads();   // sync: sRed(h0) + score partials visible

        if (havePrev && h_ws == 1)
            g_partial[(size_t)Tprev * DIM + d_ws] = sRed[d_ws] + wacc;

        if (tid < 128) {
            float s = sSc[tid] + sSc[128 + tid] + sSc[256 + tid] + sSc[384 + tid];
            sE0[buf * 128 + tid] = __expf(s);
        }
        __syncthreads();   // sync: sE[buf] visible

        if (tid < 32) {
            const float* sEc = sE0 + buf * 128;
            float e = sEc[tid] + sEc[tid + 32] + sEc[tid + 64] + sEc[tid + 96];
            e += __shfl_xor_sync(0xFFFFFFFFu, e, 16);
            e += __shfl_xor_sync(0xFFFFFFFFu, e, 8);
            e += __shfl_xor_sync(0xFFFFFFFFu, e, 4);
            e += __shfl_xor_sync(0xFFFFFFFFu, e, 2);
            e += __shfl_xor_sync(0xFFFFFFFFu, e, 1);
            if (tid == 0) g_esum[T] = e;
        }

        lastT = T; lastbuf = buf;
    }

    // ---- drain: weighted sum for the final tile ----
    {
        const float* sEc = sE0 + lastbuf * 128 + h_ws * 64;
        const float* xp = x + ((size_t)lastT * 128 + h_ws * 64) * DIM + d_ws;
        float wacc = 0.0f;
        #pragma unroll 16
        for (int t = 0; t < 64; t++)
            wacc = fmaf(sEc[t], __ldg(xp + (size_t)t * DIM), wacc);
        if (h_ws == 0) sRed[d_ws] = wacc;
        __syncthreads();
        if (h_ws == 1)
            g_partial[(size_t)lastT * DIM + d_ws] = sRed[d_ws] + wacc;
    }

    // ---- grid-wide ticket barrier (monotonic: graph-replay safe) ----
    __threadfence();
    __syncthreads();
    if (tid == 0) {
        unsigned t = atomicAdd(&g_count, 1u);
        unsigned target = (t / GRID + 1u) * GRID;
        while (atomicAdd(&g_count, 0u) < target) { __nanosleep(64); }
    }
    __syncthreads();

    // ---- finish: combine 16 splits per batch ----
    if (blockIdx.x < NBATCH && tid < DIM) {
        const int b = blockIdx.x;
        float s = 0.0f, es = 0.0f;
        #pragma unroll
        for (int sp = 0; sp < 16; sp++) {
            s  += __ldcg(&g_partial[(size_t)(b * 16 + sp) * DIM + tid]);
            es += __ldcg(&g_esum[b * 16 + sp]);
        }
        out[b * DIM + tid] = s / (es + 1e-10f);
    }
}

extern "C" void kernel_launch(void* const* d_in, const int* in_sizes, int n_in,
                              void* d_out, int out_size)
{
    const float* x    = (const float*)d_in[0];
    const float* w    = (const float*)d_in[1];
    const float* bias = (const float*)d_in[2];
    const float* cvec = (const float*)d_in[3];
    float* out = (float*)d_out;

    cudaFuncSetAttribute(attn_fused, cudaFuncAttributeMaxDynamicSharedMemorySize, SM_TOTAL);
    attn_fused<<<GRID, NTHR, SM_TOTAL>>>(x, w, bias, cvec, out);
}